// round 12
// baseline (speedup 1.0000x reference)
#include <cuda_runtime.h>
#include <cstdint>

// PureCascadedBitFFN: out[elem, j] = j-th bit (LSB=0) of
// k = ceil(distance[elem] - 0.5) (exact reduction of the sigmoid cascade).
//
// R11 showed cp.async.bulk stores profile FASTER than any STG variant
// (21.9us vs 22.4us) but lose steady-state because each block's trailing
// wait_group is fully exposed at 35% occupancy. This round pipelines it:
// double-buffered smem (2 x 16 KB), 4 consecutive 1024-quad tiles per
// block; tile t+1 is computed while tile t's bulk store drains. Only
// buffer reuse waits (read <= 1); the exposed wait shrinks to the last
// tile per block.

__global__ __launch_bounds__(256) void cascaded_bits_tma_pipe_kernel(
    const float* __restrict__ dist,
    float4* __restrict__ out)
{
    __shared__ float4 buf[2][1024];          // 2 x 16 KB staging
    const int tid = threadIdx.x;

    #pragma unroll
    for (int t = 0; t < 4; t++) {
        const int b = t & 1;

        // Before overwriting a buffer, ensure its previous bulk store's
        // SMEM reads have completed (at most 1 younger group pending).
        if (t >= 2) {
            if (tid == 0)
                asm volatile("cp.async.bulk.wait_group.read 1;" ::: "memory");
            __syncthreads();
        }

        const int base = blockIdx.x * 4096 + t * 1024;   // first quad of tile

        // Compute 4 quads/thread into smem (conflict-free STS.128).
        #pragma unroll
        for (int i = 0; i < 4; i++) {
            const int lq = tid + i * 256;     // local quad in [0, 1024)
            const int q  = base + lq;
            const float r = __ldg(&dist[q >> 2]);
            const int k = __float2int_ru(r - 0.5f);  // exact round-half-down
            const int bit = (q & 3) << 2;     // starting bit: 0,4,8,12
            float4 v;
            v.x = __int_as_float(((k >> (bit + 0)) & 1) * 0x3F800000);
            v.y = __int_as_float(((k >> (bit + 1)) & 1) * 0x3F800000);
            v.z = __int_as_float(((k >> (bit + 2)) & 1) * 0x3F800000);
            v.w = __int_as_float(((k >> (bit + 3)) & 1) * 0x3F800000);
            buf[b][lq] = v;
        }
        __syncthreads();
        asm volatile("fence.proxy.async.shared::cta;" ::: "memory");

        if (tid == 0) {
            uint32_t saddr;
            asm("{ .reg .u64 tt; cvta.to.shared.u64 tt, %1; cvt.u32.u64 %0, tt; }"
                : "=r"(saddr) : "l"(&buf[b][0]));
            asm volatile(
                "cp.async.bulk.global.shared::cta.bulk_group [%0], [%1], %2;"
                :: "l"(out + base), "r"(saddr), "n"(16384) : "memory");
            asm volatile("cp.async.bulk.commit_group;" ::: "memory");
        }
    }

    // Drain before smem is released at block exit.
    if (tid == 0)
        asm volatile("cp.async.bulk.wait_group.read 0;" ::: "memory");
}

extern "C" void kernel_launch(void* const* d_in, const int* in_sizes, int n_in,
                              void* d_out, int out_size)
{
    const float* dist = (const float*)d_in[0];
    float4* out = (float4*)d_out;

    int n_elems = in_sizes[0];            // 512*4096 = 2,097,152
    int nquads  = n_elems * 4;            // 8,388,608
    int blocks  = nquads / 4096;          // 2048 (exact, 4 tiles per block)

    cascaded_bits_tma_pipe_kernel<<<blocks, 256>>>(dist, out);
}

// round 13
// speedup vs baseline: 1.1889x; 1.1889x over previous
#include <cuda_runtime.h>

// PureCascadedBitFFN: out[elem, j] = j-th bit (LSB=0) of
// k = ceil(distance[elem] - 0.5) (exact reduction of the 16-step sigmoid
// cascade in the reference: sigmoid(S*x) > 0.5  <=>  x > 0, so the cascade
// collapses to round-half-down + bit extraction).
//
// 128 MB f32 output, never re-read: pinned at the GB300 HBM write wall.
// Steady-state 23.04us = 5.9 TB/s total DRAM traffic (~74% of 8 TB/s spec);
// LSU (29%), ALU (34%), LTS (51%) all have headroom -> HBM write drain is
// the binding wall and the output bytes are irreducible.
//
// Falsified alternatives (12 rounds): smem read-dedup (neutral), persistent
// grid (+2us), __stwt write-through (+4us), 16 quads/thread @ grid=1024
// (+1.6us, occupancy loss), cp.async.bulk TMA stores unpipelined (+4.1us)
// and double-buffered pipelined (+4.4us) - TMA bulk writes stall harder
// against the steady-state dirty-L2 victim drain than sector-level STG.
//
// FINAL config (R8, reconfirmed R10): 512-thread blocks, 4096-quad tiles,
// grid=2048. Each thread: 8 quads strided by 512 -> 8 coalesced 2KB
// block-wide STG.128 bursts; front-batched __ldg reads; __stcs evict-first
// (L2 buffers + burst-forms the DRAM drain); bits materialized by integer
// select of 0x3F800000 (no convert pipe).

__global__ __launch_bounds__(512) void cascaded_bits_kernel(
    const float* __restrict__ dist,
    float4* __restrict__ out)
{
    const int base = blockIdx.x * 4096 + threadIdx.x;

    float r[8];
    #pragma unroll
    for (int i = 0; i < 8; i++)
        r[i] = __ldg(&dist[(base + i * 512) >> 2]);

    int k[8];
    #pragma unroll
    for (int i = 0; i < 8; i++)
        k[i] = __float2int_ru(r[i] - 0.5f);   // exact round-half-down

    #pragma unroll
    for (int i = 0; i < 8; i++) {
        const int q   = base + i * 512;
        const int bit = (q & 3) << 2;         // starting bit: 0,4,8,12
        float4 v;
        v.x = __int_as_float(((k[i] >> (bit + 0)) & 1) * 0x3F800000);
        v.y = __int_as_float(((k[i] >> (bit + 1)) & 1) * 0x3F800000);
        v.z = __int_as_float(((k[i] >> (bit + 2)) & 1) * 0x3F800000);
        v.w = __int_as_float(((k[i] >> (bit + 3)) & 1) * 0x3F800000);
        __stcs(&out[q], v);                   // streaming: evict-first in L2
    }
}

extern "C" void kernel_launch(void* const* d_in, const int* in_sizes, int n_in,
                              void* d_out, int out_size)
{
    const float* dist = (const float*)d_in[0];
    float4* out = (float4*)d_out;

    int n_elems = in_sizes[0];            // 512*4096 = 2,097,152
    int nquads  = n_elems * 4;            // 8,388,608
    int blocks  = nquads / 4096;          // 2048 (exact)

    cascaded_bits_kernel<<<blocks, 512>>>(dist, out);
}

// round 14
// speedup vs baseline: 1.1922x; 1.0028x over previous
#include <cuda_runtime.h>

// PureCascadedBitFFN: out[elem, j] = j-th bit (LSB=0) of
// k = ceil(distance[elem] - 0.5) (exact reduction of the 16-step sigmoid
// cascade in the reference: sigmoid(S*x) > 0.5  <=>  x > 0, so the cascade
// collapses to round-half-down + bit extraction).
//
// 128 MB f32 output, never re-read: pinned at the GB300 HBM write wall.
// Steady-state 23.04us (deterministic across R8/R10/R13) = 5.9 TB/s total
// DRAM traffic (~74% of 8 TB/s spec); LSU (29%), ALU (33%), LTS (50%) all
// have headroom -> HBM write drain is the binding wall and the output
// bytes are irreducible.
//
// Falsified alternatives (13 rounds): smem read-dedup (neutral), persistent
// grid (+2us), __stwt write-through (+4us), 16 quads/thread @ grid=1024
// (+1.6us, occupancy loss), cp.async.bulk TMA stores unpipelined (+4.1us)
// and double-buffered pipelined (+4.4us) - TMA bulk writes stall harder
// against the steady-state dirty-L2 victim drain than sector-level STG.
//
// FINAL config: 512-thread blocks, 4096-quad tiles, grid=2048. Each thread:
// 8 quads strided by 512 -> 8 coalesced 2KB block-wide STG.128 bursts;
// front-batched __ldg reads; __stcs evict-first (L2 buffers + burst-forms
// the DRAM drain); bits materialized by integer select of 0x3F800000.

__global__ __launch_bounds__(512) void cascaded_bits_kernel(
    const float* __restrict__ dist,
    float4* __restrict__ out)
{
    const int base = blockIdx.x * 4096 + threadIdx.x;

    float r[8];
    #pragma unroll
    for (int i = 0; i < 8; i++)
        r[i] = __ldg(&dist[(base + i * 512) >> 2]);

    int k[8];
    #pragma unroll
    for (int i = 0; i < 8; i++)
        k[i] = __float2int_ru(r[i] - 0.5f);   // exact round-half-down

    #pragma unroll
    for (int i = 0; i < 8; i++) {
        const int q   = base + i * 512;
        const int bit = (q & 3) << 2;         // starting bit: 0,4,8,12
        float4 v;
        v.x = __int_as_float(((k[i] >> (bit + 0)) & 1) * 0x3F800000);
        v.y = __int_as_float(((k[i] >> (bit + 1)) & 1) * 0x3F800000);
        v.z = __int_as_float(((k[i] >> (bit + 2)) & 1) * 0x3F800000);
        v.w = __int_as_float(((k[i] >> (bit + 3)) & 1) * 0x3F800000);
        __stcs(&out[q], v);                   // streaming: evict-first in L2
    }
}

extern "C" void kernel_launch(void* const* d_in, const int* in_sizes, int n_in,
                              void* d_out, int out_size)
{
    const float* dist = (const float*)d_in[0];
    float4* out = (float4*)d_out;

    int n_elems = in_sizes[0];            // 512*4096 = 2,097,152
    int nquads  = n_elems * 4;            // 8,388,608
    int blocks  = nquads / 4096;          // 2048 (exact)

    cascaded_bits_kernel<<<blocks, 512>>>(dist, out);
}